// round 7
// baseline (speedup 1.0000x reference)
#include <cuda_runtime.h>
#include <cstdint>
#include <float.h>
#include <limits.h>

#define CONF_THRESH 0.25f
#define CHUNK_ROWS  64
#define CHUNK_F     (CHUNK_ROWS * 80)           // 5120 floats
#define CHUNK_F4    (CHUNK_F / 4)               // 1280 float4 = 20 KB
#define THREADS     256
#define WARPS       (THREADS / 32)
#define GRID        740                         // 148 SMs x 5 blocks (smem cap)

// Scratch (__device__ globals; no cudaMalloc allowed).
__device__ float        g_partials[4096];
__device__ int          g_blockmin[4096];
__device__ unsigned int g_counter = 0;          // modulo ticket: no reset needed

__device__ __forceinline__ uint32_t smem_u32(const void* p) {
    uint32_t a;
    asm("{ .reg .u64 t; cvta.to.shared.u64 t, %1; cvt.u32.u64 %0, t; }"
        : "=r"(a) : "l"(p));
    return a;
}

__device__ __forceinline__ void stage_chunk(uint32_t sdst, const float4* gsrc) {
    // 1280 float4 staged by 256 threads: 5 x 16B each
    #pragma unroll
    for (int k = 0; k < 5; k++) {
        const int idx = threadIdx.x + k * THREADS;
        asm volatile("cp.async.cg.shared.global [%0], [%1], 16;"
                     :: "r"(sdst + idx * 16), "l"(gsrc + idx) : "memory");
    }
}

__global__ void __launch_bounds__(THREADS)
fused_kernel(const float* __restrict__ post, float* __restrict__ out, int K) {
    __shared__ alignas(16) float tile[2][CHUNK_F];
    __shared__ int   sLast;
    __shared__ float sWs[WARPS];
    __shared__ int   sWm[WARPS];

    const int tid    = threadIdx.x;
    const int lane   = tid & 31;
    const int wid    = tid >> 5;
    const int stride = gridDim.x;
    const int nchunks = (K + CHUNK_ROWS - 1) / CHUNK_ROWS;   // 2048

    const float4* base = reinterpret_cast<const float4*>(post);
    const uint32_t s0 = smem_u32(tile[0]);
    const uint32_t s1 = smem_u32(tile[1]);

    // ---- prologue: prefetch first two chunks ----
    const int c0 = blockIdx.x;
    if (c0 < nchunks) stage_chunk(s0, base + (size_t)c0 * CHUNK_F4);
    asm volatile("cp.async.commit_group;" ::: "memory");
    if (c0 + stride < nchunks)
        stage_chunk(s1, base + (size_t)(c0 + stride) * CHUNK_F4);
    asm volatile("cp.async.commit_group;" ::: "memory");

    // ---- main loop over this block's chunks ----
    const int sub = tid & 3;          // quarter of a row
    const int r0  = tid >> 2;         // 0..63 (row within chunk)
    float wsum = 0.0f;
    int   wmin = INT_MAX;
    int   s    = 0;

    for (int c = c0; c < nchunks; c += stride) {
        asm volatile("cp.async.wait_group 1;" ::: "memory");  // oldest group done
        __syncthreads();

        const float* t = tile[s];
        const float4* rp = reinterpret_cast<const float4*>(t + r0 * 80) + sub * 5;
        float m = -FLT_MAX;
        #pragma unroll
        for (int i = 0; i < 5; i++) {
            float4 v = rp[i];
            m = fmaxf(m, fmaxf(fmaxf(v.x, v.y), fmaxf(v.z, v.w)));
        }
        m = fmaxf(m, __shfl_xor_sync(0xffffffffu, m, 1));
        m = fmaxf(m, __shfl_xor_sync(0xffffffffu, m, 2));
        const int grow = c * CHUNK_ROWS + r0;
        if (sub == 0 && grow < K) {
            wsum += m;
            if (m < CONF_THRESH) wmin = min(wmin, grow);
        }
        __syncthreads();              // everyone done reading stage s

        const int cn = c + 2 * stride;
        if (cn < nchunks)
            stage_chunk(s ? s1 : s0, base + (size_t)cn * CHUNK_F4);
        asm volatile("cp.async.commit_group;" ::: "memory");  // empty group ok
        s ^= 1;
    }
    asm volatile("cp.async.wait_group 0;" ::: "memory");

    // ---- warp reduce ----
    #pragma unroll
    for (int o = 16; o > 0; o >>= 1) {
        wsum += __shfl_xor_sync(0xffffffffu, wsum, o);
        wmin  = min(wmin, __shfl_xor_sync(0xffffffffu, wmin, o));
    }
    if (lane == 0) { sWs[wid] = wsum; sWm[wid] = wmin; }
    __syncthreads();

    // ---- block reduce + ticket ----
    if (tid < 32) {
        float sm_ = (lane < WARPS) ? sWs[lane] : 0.0f;
        int   mn  = (lane < WARPS) ? sWm[lane] : INT_MAX;
        #pragma unroll
        for (int o = 4; o > 0; o >>= 1) {
            sm_ += __shfl_xor_sync(0xffffffffu, sm_, o);
            mn   = min(mn, __shfl_xor_sync(0xffffffffu, mn, o));
        }
        if (lane == 0) {
            g_partials[blockIdx.x] = sm_;
            g_blockmin[blockIdx.x] = mn;
            __threadfence();
            unsigned int t = atomicAdd(&g_counter, 1u);
            sLast = ((t % gridDim.x) == gridDim.x - 1) ? 1 : 0;
        }
    }
    __syncthreads();
    if (!sLast) return;

    // ================= elected last block: final reduce =================
    float fsum = 0.0f;
    int   fmin = INT_MAX;
    for (int i = tid; i < gridDim.x; i += THREADS) {
        fsum += g_partials[i];
        fmin  = min(fmin, g_blockmin[i]);
    }
    #pragma unroll
    for (int o = 16; o > 0; o >>= 1) {
        fsum += __shfl_xor_sync(0xffffffffu, fsum, o);
        fmin  = min(fmin, __shfl_xor_sync(0xffffffffu, fmin, o));
    }
    __shared__ float fWs[WARPS];
    __shared__ int   fWm[WARPS];
    __shared__ int   sCut;
    if (lane == 0) { fWs[wid] = fsum; fWm[wid] = fmin; }
    __syncthreads();
    if (tid < 32) {
        float s2  = (lane < WARPS) ? fWs[lane] : 0.0f;
        int   mn2 = (lane < WARPS) ? fWm[lane] : INT_MAX;
        #pragma unroll
        for (int o = 4; o > 0; o >>= 1) {
            s2  += __shfl_xor_sync(0xffffffffu, s2, o);
            mn2  = min(mn2, __shfl_xor_sync(0xffffffffu, mn2, o));
        }
        if (lane == 0) {
            int cutoff = min(mn2, K);
            sCut = cutoff;
            if (cutoff >= K) out[0] = s2;   // common path
        }
    }
    __syncthreads();

    // ---- rare fixup (P ~ 0.25^80): recompute prefix [0, cutoff) from gmem ----
    const int cutoff = sCut;
    if (cutoff < K) {
        float fs = 0.0f;
        for (int r = tid; r < cutoff; r += THREADS) {
            const float4* rp = reinterpret_cast<const float4*>(post + (size_t)r * 80);
            float m = -FLT_MAX;
            #pragma unroll
            for (int i = 0; i < 20; i++) {
                float4 v = __ldg(rp + i);
                m = fmaxf(m, fmaxf(fmaxf(v.x, v.y), fmaxf(v.z, v.w)));
            }
            fs += m;
        }
        #pragma unroll
        for (int o = 16; o > 0; o >>= 1)
            fs += __shfl_xor_sync(0xffffffffu, fs, o);
        if (lane == 0) fWs[wid] = fs;
        __syncthreads();
        if (tid < 32) {
            float f2 = (lane < WARPS) ? fWs[lane] : 0.0f;
            #pragma unroll
            for (int o = 4; o > 0; o >>= 1)
                f2 += __shfl_xor_sync(0xffffffffu, f2, o);
            if (lane == 0) out[0] = f2;
        }
    }
}

extern "C" void kernel_launch(void* const* d_in, const int* in_sizes, int n_in,
                              void* d_out, int out_size) {
    const float* post = (const float*)d_in[0];
    float* out = (float*)d_out;

    const int n_rows = in_sizes[0] / 80;   // 262144
    const int K      = n_rows / 2;         // ratio = 0.5 -> 131072

    const int nchunks = (K + CHUNK_ROWS - 1) / CHUNK_ROWS;
    const int grid = GRID < nchunks ? GRID : nchunks;   // persistent grid
    fused_kernel<<<grid, THREADS>>>(post, out, K);
}